// round 16
// baseline (speedup 1.0000x reference)
#include <cuda_runtime.h>
#include <cuda_fp16.h>
#include <cstdint>

// GIN: 5 layers, N=20000 nodes, E=320000 edges, HIDDEN=64, M=8.
//  - CSR build per launch (vectorized histogram + shfl scan + fill).
//  - h/z fp16, L2-resident. k_gather: fp16 CSR gather + local BN-affine -> z.
//  - k_layer0 + k_mlp: HMMA GEMMs, weight smem rows padded to 144B
//    (conflict-free ldmatrix). k_mlp: 16 nodes/block. Layer-4 epilogue
//    accumulates the mean-pool. k_final folds layer-4 BN into the head.

#define N_NODES 20000
#define N_EDGES 320000
#define HID 64
#define MDIM 8
#define FEAT (HID*MDIM)   // 512 elements per node
#define WPAD 72           // padded halves per weight row (144B, 9 uint4)

typedef unsigned long long ull;

// ---------------- device scratch ----------------
__device__ __half g_hbuf[N_NODES * FEAT];   // h fp16 (gather + pool source)
__device__ __half g_z16[N_NODES * FEAT];    // z fp16 scratch
__device__ int    g_rowptr[N_NODES + 1];
__device__ int    g_count[N_NODES];
__device__ int    g_fill[N_NODES];
__device__ int    g_srce[N_EDGES];
__device__ float  g_stats[5 * 128];         // per layer: sum[64], sumsq[64]
__device__ __half g_W1h[4 * 4096];          // W1 layers 1..4, [o][c] fp16
__device__ __half g_W2h[5 * 4096];          // W2 layers 0..4, [o][c] fp16
__device__ float  g_pool[FEAT];
__device__ int    g_is64;

// ---------------- helpers ----------------
__device__ __forceinline__ uint32_t smem_u32(const void* p) {
    return (uint32_t)__cvta_generic_to_shared(p);
}
__device__ __forceinline__ void ldmA(unsigned a[4], uint32_t addr) {
    asm volatile("ldmatrix.sync.aligned.m8n8.x4.shared.b16 {%0,%1,%2,%3}, [%4];"
        : "=r"(a[0]), "=r"(a[1]), "=r"(a[2]), "=r"(a[3]) : "r"(addr));
}
__device__ __forceinline__ void ldmBt(unsigned b[2], uint32_t addr) {
    asm volatile("ldmatrix.sync.aligned.m8n8.x2.trans.shared.b16 {%0,%1}, [%2];"
        : "=r"(b[0]), "=r"(b[1]) : "r"(addr));
}
__device__ __forceinline__ void mma16816(float d[4], const unsigned a[4], const unsigned b[2]) {
    asm volatile("mma.sync.aligned.m16n8k16.row.col.f32.f16.f16.f32 "
        "{%0,%1,%2,%3}, {%4,%5,%6,%7}, {%8,%9}, {%0,%1,%2,%3};"
        : "+f"(d[0]), "+f"(d[1]), "+f"(d[2]), "+f"(d[3])
        : "r"(a[0]), "r"(a[1]), "r"(a[2]), "r"(a[3]), "r"(b[0]), "r"(b[1]));
}

// ---------------- setup: init + dtype detect + weight fp16 prep ----------------
__global__ void k_init(const void* ei, const float* __restrict__ w1,
                       const float* __restrict__ w2) {
    __shared__ int s_ok;
    if (threadIdx.x == 0) s_ok = 1;
    __syncthreads();
    int i = blockIdx.x * blockDim.x + threadIdx.x;
    if (i < N_NODES) { g_count[i] = 0; g_fill[i] = 0; }
    if (i < 5 * 128) g_stats[i] = 0.f;
    if (i < FEAT)    g_pool[i] = 0.f;
    if (i < 4 * 4096) g_W1h[i] = __float2half(w1[i]);
    if (i < 5 * 4096) g_W2h[i] = __float2half(w2[i]);
    if (blockIdx.x == 0 && threadIdx.x < 64) {
        if (((const ull*)ei)[threadIdx.x] >= (ull)N_NODES) atomicExch(&s_ok, 0);
    }
    __syncthreads();
    if (blockIdx.x == 0 && threadIdx.x == 0) g_is64 = s_ok;
}

// histogram: 4 edges per thread, vectorized loads
__global__ void k_hist(const void* ei) {
    int i = blockIdx.x * blockDim.x + threadIdx.x;
    if (i * 4 >= N_EDGES) return;
    int d0, d1, d2, d3;
    if (g_is64) {
        const longlong2* pd = (const longlong2*)((const long long*)ei + N_EDGES);
        longlong2 a = pd[i * 2], b = pd[i * 2 + 1];
        d0 = (int)a.x; d1 = (int)a.y; d2 = (int)b.x; d3 = (int)b.y;
    } else {
        int4 a = ((const int4*)((const int*)ei + N_EDGES))[i];
        d0 = a.x; d1 = a.y; d2 = a.z; d3 = a.w;
    }
    atomicAdd(&g_count[d0], 1);
    atomicAdd(&g_count[d1], 1);
    atomicAdd(&g_count[d2], 1);
    atomicAdd(&g_count[d3], 1);
}

// shfl scan; int4 loads AND int4 stores
__global__ void k_scan() {   // 1024 threads
    __shared__ int warpsum[32];
    const int CH = 20;
    int t = threadIdx.x;
    int lane = t & 31, wid = t >> 5;
    int base = t * CH;
    int raw[CH];
    bool full = (base + CH <= N_NODES);
    if (full) {
#pragma unroll
        for (int v4 = 0; v4 < 5; v4++) {
            int4 v = *(const int4*)(g_count + base + v4 * 4);
            raw[v4 * 4 + 0] = v.x; raw[v4 * 4 + 1] = v.y;
            raw[v4 * 4 + 2] = v.z; raw[v4 * 4 + 3] = v.w;
        }
    } else {
#pragma unroll
        for (int j = 0; j < CH; j++)
            raw[j] = (base + j < N_NODES) ? g_count[base + j] : 0;
    }
    int vals[CH];
    int local = 0;
#pragma unroll
    for (int j = 0; j < CH; j++) { vals[j] = local; local += raw[j]; }
    int inc = local;
#pragma unroll
    for (int off = 1; off < 32; off <<= 1) {
        int v = __shfl_up_sync(0xffffffffu, inc, off);
        if (lane >= off) inc += v;
    }
    if (lane == 31) warpsum[wid] = inc;
    __syncthreads();
    if (wid == 0) {
        int v = warpsum[lane];
        int inc2 = v;
#pragma unroll
        for (int off = 1; off < 32; off <<= 1) {
            int u = __shfl_up_sync(0xffffffffu, inc2, off);
            if (lane >= off) inc2 += u;
        }
        warpsum[lane] = inc2 - v;
    }
    __syncthreads();
    int toff = warpsum[wid] + inc - local;
    if (full) {
#pragma unroll
        for (int v4 = 0; v4 < 5; v4++) {
            int4 st;
            st.x = toff + vals[v4 * 4 + 0];
            st.y = toff + vals[v4 * 4 + 1];
            st.z = toff + vals[v4 * 4 + 2];
            st.w = toff + vals[v4 * 4 + 3];
            *(int4*)(g_rowptr + base + v4 * 4) = st;
        }
    } else {
#pragma unroll
        for (int j = 0; j < CH; j++)
            if (base + j < N_NODES) g_rowptr[base + j] = toff + vals[j];
    }
    if (t == 1023) g_rowptr[N_NODES] = toff + local;
}

// fill: 2 edges per thread (more TLP for the latency-bound atomic+scatter chain)
__global__ void k_fill(const void* ei) {
    int i = blockIdx.x * blockDim.x + threadIdx.x;
    if (i * 2 >= N_EDGES) return;
    int s0, s1, d0, d1;
    if (g_is64) {
        longlong2 a = ((const longlong2*)ei)[i];
        longlong2 c = ((const longlong2*)((const long long*)ei + N_EDGES))[i];
        s0 = (int)a.x; s1 = (int)a.y;
        d0 = (int)c.x; d1 = (int)c.y;
    } else {
        int2 a = ((const int2*)ei)[i];
        int2 c = ((const int2*)((const int*)ei + N_EDGES))[i];
        s0 = a.x; s1 = a.y;
        d0 = c.x; d1 = c.y;
    }
    g_srce[g_rowptr[d0] + atomicAdd(&g_fill[d0], 1)] = s0;
    g_srce[g_rowptr[d1] + atomicAdd(&g_fill[d1], 1)] = s1;
}

// ---------------- layer 0: x-gather + outer-product GEMM1 + HMMA GEMM2 ----------
__global__ void __launch_bounds__(256) k_layer0(
    const float* __restrict__ x, const float* __restrict__ w10,
    const float* __restrict__ b1, const float* __restrict__ b2) {
    __shared__ __half sW2[64 * WPAD];
    __shared__ __half sZ[8 * FEAT];
    __shared__ float sStats[128];
    __shared__ float sW10[64], sB1[64], sB2[64];
    __shared__ float sZ0[64];
    int t = threadIdx.x;
    int w = t >> 5, lane = t & 31;
    if (t < 128) sStats[t] = 0.f;
    if (t < 64) { sW10[t] = w10[t]; sB1[t] = b1[t]; sB2[t] = b2[t]; }
    const uint4* w2src = (const uint4*)g_W2h;
#pragma unroll
    for (int rep = 0; rep < 2; rep++) {
        int j = t + rep * 256;
        int o = j >> 3, c8 = j & 7;
        ((uint4*)sW2)[o * 9 + c8] = w2src[j];
    }
    __syncthreads();

    int n = (blockIdx.x << 3) + w;
    int m = lane & 7, g = lane >> 3;
    int rs = g_rowptr[n], re = g_rowptr[n + 1];
    float z = (g == 0) ? x[n * 8 + m] : 0.f;
    for (int e = rs + g; e < re; e += 4)
        z += x[g_srce[e] * 8 + m];
    z += __shfl_xor_sync(0xffffffffu, z, 8);
    z += __shfl_xor_sync(0xffffffffu, z, 16);
    if (lane < 8) sZ0[w * 8 + m] = z;
    __syncwarp();
    float zf[8];
#pragma unroll
    for (int j = 0; j < 8; j++) zf[j] = sZ0[w * 8 + j];
    int orow0 = lane * 2;
#pragma unroll
    for (int r2 = 0; r2 < 2; r2++) {
        int o = orow0 + r2;
        float wv = sW10[o], b = sB1[o];
        __half2 p0 = __floats2half2_rn(fmaxf(wv * zf[0] + b, 0.f), fmaxf(wv * zf[1] + b, 0.f));
        __half2 p1 = __floats2half2_rn(fmaxf(wv * zf[2] + b, 0.f), fmaxf(wv * zf[3] + b, 0.f));
        __half2 p2 = __floats2half2_rn(fmaxf(wv * zf[4] + b, 0.f), fmaxf(wv * zf[5] + b, 0.f));
        __half2 p3 = __floats2half2_rn(fmaxf(wv * zf[6] + b, 0.f), fmaxf(wv * zf[7] + b, 0.f));
        uint4 hv;
        hv.x = *(unsigned*)&p0; hv.y = *(unsigned*)&p1;
        hv.z = *(unsigned*)&p2; hv.w = *(unsigned*)&p3;
        *(uint4*)(sZ + (w << 9) + o * 8) = hv;
    }
    __syncwarp();

    uint32_t zbase = smem_u32(sZ + w * FEAT);
    int r = lane >> 2, q = lane & 3;
    int arow = lane & 15, acol = (lane >> 4) << 3;
    unsigned bf[4][2];
#pragma unroll
    for (int k = 0; k < 4; k++)
        ldmBt(bf[k], zbase + ((k * 16 + (lane & 15)) * 8) * 2);
    uint32_t w2base = smem_u32(sW2);
    float acc[4][4];
#pragma unroll
    for (int ot = 0; ot < 4; ot++) {
#pragma unroll
        for (int i = 0; i < 4; i++) acc[ot][i] = 0.f;
#pragma unroll
        for (int k = 0; k < 4; k++) {
            unsigned af[4];
            ldmA(af, w2base + (ot * 16 + arow) * (WPAD * 2) + (k * 16 + acol) * 2);
            mma16816(acc[ot], af, bf[k]);
        }
    }
    __half* hrow = g_hbuf + (size_t)n * FEAT;
#pragma unroll
    for (int ot = 0; ot < 4; ot++) {
        int oa = ot * 16 + r, ob = oa + 8;
        float ba = sB2[oa], bb = sB2[ob];
        float f0 = fmaxf(acc[ot][0] + ba, 0.f), f1 = fmaxf(acc[ot][1] + ba, 0.f);
        float f2 = fmaxf(acc[ot][2] + bb, 0.f), f3 = fmaxf(acc[ot][3] + bb, 0.f);
        *(__half2*)(hrow + oa * 8 + 2 * q) = __floats2half2_rn(f0, f1);
        *(__half2*)(hrow + ob * 8 + 2 * q) = __floats2half2_rn(f2, f3);
        float sa = f0 + f1, qa = f0 * f0 + f1 * f1;
        float sb = f2 + f3, qb = f2 * f2 + f3 * f3;
        sa += __shfl_xor_sync(0xffffffffu, sa, 1); sa += __shfl_xor_sync(0xffffffffu, sa, 2);
        qa += __shfl_xor_sync(0xffffffffu, qa, 1); qa += __shfl_xor_sync(0xffffffffu, qa, 2);
        sb += __shfl_xor_sync(0xffffffffu, sb, 1); sb += __shfl_xor_sync(0xffffffffu, sb, 2);
        qb += __shfl_xor_sync(0xffffffffu, qb, 1); qb += __shfl_xor_sync(0xffffffffu, qb, 2);
        if (q == 0) {
            atomicAdd(&sStats[oa], sa);
            atomicAdd(&sStats[64 + oa], qa);
            atomicAdd(&sStats[ob], sb);
            atomicAdd(&sStats[64 + ob], qb);
        }
    }
    __syncthreads();
    if (t < 128) atomicAdd(&g_stats[t], sStats[t]);
}

// ---------------- gather (layers 1..4): fp16 CSR gather + local BN affine ----
__device__ __forceinline__ void acc8(float a[8], uint4 v) {
    float2 p;
    p = __half22float2(*(const __half2*)&v.x); a[0] += p.x; a[1] += p.y;
    p = __half22float2(*(const __half2*)&v.y); a[2] += p.x; a[3] += p.y;
    p = __half22float2(*(const __half2*)&v.z); a[4] += p.x; a[5] += p.y;
    p = __half22float2(*(const __half2*)&v.w); a[6] += p.x; a[7] += p.y;
}

__global__ void __launch_bounds__(256) k_gather(
    int layer, const float* __restrict__ gamma, const float* __restrict__ beta) {
    __shared__ float sSc[64], sSh[64];
    const uint4* __restrict__ in = (const uint4*)g_hbuf;
    int t = threadIdx.x;
    if (t < 64) {
        const float* st = g_stats + (layer - 1) * 128;
        float inv = 1.0f / 160000.0f;
        float mean = st[t] * inv;
        float var = st[64 + t] * inv - mean * mean;
        float sc = gamma[t] * rsqrtf(var + 1e-5f);
        sSc[t] = sc;
        sSh[t] = beta[t] - mean * sc;
    }
    __syncthreads();
    int grp = t >> 6;
    int l = t & 63;
    int n = (blockIdx.x << 2) + grp;
    int rs = g_rowptr[n], re = g_rowptr[n + 1];
    float sc = sSc[l], sh = sSh[l];
    float a[8] = {0,0,0,0,0,0,0,0}, b[8] = {0,0,0,0,0,0,0,0};
    acc8(a, in[(size_t)n * 64 + l]);   // self
    int e = rs;
    for (; e + 4 <= re; e += 4) {
        uint4 v0 = in[(size_t)g_srce[e]     * 64 + l];
        uint4 v1 = in[(size_t)g_srce[e + 1] * 64 + l];
        uint4 v2 = in[(size_t)g_srce[e + 2] * 64 + l];
        uint4 v3 = in[(size_t)g_srce[e + 3] * 64 + l];
        acc8(a, v0); acc8(b, v1); acc8(a, v2); acc8(b, v3);
    }
    for (; e < re; e++) acc8(a, in[(size_t)g_srce[e] * 64 + l]);
    float shd = sh * (float)(re - rs + 1);
    float f0 = sc * (a[0] + b[0]) + shd, f1 = sc * (a[1] + b[1]) + shd;
    float f2 = sc * (a[2] + b[2]) + shd, f3 = sc * (a[3] + b[3]) + shd;
    float f4 = sc * (a[4] + b[4]) + shd, f5 = sc * (a[5] + b[5]) + shd;
    float f6 = sc * (a[6] + b[6]) + shd, f7 = sc * (a[7] + b[7]) + shd;
    __half2 h0 = __floats2half2_rn(f0, f1);
    __half2 h1 = __floats2half2_rn(f2, f3);
    __half2 h2 = __floats2half2_rn(f4, f5);
    __half2 h3 = __floats2half2_rn(f6, f7);
    uint4 hv;
    hv.x = *(unsigned*)&h0; hv.y = *(unsigned*)&h1;
    hv.z = *(unsigned*)&h2; hv.w = *(unsigned*)&h3;
    *(uint4*)(g_z16 + (size_t)n * FEAT + (l << 3)) = hv;
}

// ---------------- MLP (layers 1..4): HMMA GEMM pair, 16 nodes/block ----------
__global__ void __launch_bounds__(512) k_mlp(
    int layer, const float* __restrict__ b1, const float* __restrict__ b2) {
    __shared__ __half sW1[64 * WPAD];
    __shared__ __half sW2[64 * WPAD];
    __shared__ __half sZ[16 * FEAT];    // 16 node tiles [c64][m8]
    __shared__ float sStats[128];
    __shared__ float sPool[FEAT];
    __shared__ float sB1[64], sB2[64];
    int t = threadIdx.x;
    int w = t >> 5, lane = t & 31;      // w: 0..15, node within block
    if (t < 128) sStats[t] = 0.f;
    if (t < 64) { sB1[t] = b1[t]; sB2[t] = b2[t]; }
    if (layer == 4) sPool[t] = 0.f;     // 512 threads cover FEAT
    const uint4* w1src = (const uint4*)(g_W1h + (size_t)(layer - 1) * 4096);
    const uint4* w2src = (const uint4*)(g_W2h + (size_t)layer * 4096);
    const uint4* zsrc  = (const uint4*)(g_z16 + (size_t)(blockIdx.x << 4) * FEAT);
    {
        int o = t >> 3, c8 = t & 7;     // 512 threads = 512 uint4 per matrix
        ((uint4*)sW1)[o * 9 + c8] = w1src[t];
        ((uint4*)sW2)[o * 9 + c8] = w2src[t];
    }
    ((uint4*)sZ)[t]       = zsrc[t];
    ((uint4*)sZ)[t + 512] = zsrc[t + 512];
    __syncthreads();

    int n = (blockIdx.x << 4) + w;
    uint32_t zbase = smem_u32(sZ + w * FEAT);
    int r = lane >> 2, q = lane & 3;
    int arow = lane & 15, acol = (lane >> 4) << 3;

    // ---- GEMM1 ----
    unsigned bf[4][2];
#pragma unroll
    for (int k = 0; k < 4; k++)
        ldmBt(bf[k], zbase + ((k * 16 + (lane & 15)) * 8) * 2);
    uint32_t w1base = smem_u32(sW1);
    float acc[4][4];
#pragma unroll
    for (int ot = 0; ot < 4; ot++) {
#pragma unroll
        for (int i = 0; i < 4; i++) acc[ot][i] = 0.f;
#pragma unroll
        for (int k = 0; k < 4; k++) {
            unsigned af[4];
            ldmA(af, w1base + (ot * 16 + arow) * (WPAD * 2) + (k * 16 + acol) * 2);
            mma16816(acc[ot], af, bf[k]);
        }
    }
#pragma unroll
    for (int ot = 0; ot < 4; ot++) {
        int oa = ot * 16 + r, ob = oa + 8;
        float ba = sB1[oa], bb = sB1[ob];
        __half2 ya = __floats2half2_rn(fmaxf(acc[ot][0] + ba, 0.f), fmaxf(acc[ot][1] + ba, 0.f));
        __half2 yb = __floats2half2_rn(fmaxf(acc[ot][2] + bb, 0.f), fmaxf(acc[ot][3] + bb, 0.f));
        *(__half2*)(sZ + w * FEAT + oa * 8 + 2 * q) = ya;
        *(__half2*)(sZ + w * FEAT + ob * 8 + 2 * q) = yb;
    }
    __syncwarp();

    // ---- GEMM2 ----
#pragma unroll
    for (int k = 0; k < 4; k++)
        ldmBt(bf[k], zbase + ((k * 16 + (lane & 15)) * 8) * 2);
    uint32_t w2base = smem_u32(sW2);
#pragma unroll
    for (int ot = 0; ot < 4; ot++) {
#pragma unroll
        for (int i = 0; i < 4; i++) acc[ot][i] = 0.f;
#pragma unroll
        for (int k = 0; k < 4; k++) {
            unsigned af[4];
            ldmA(af, w2base + (ot * 16 + arow) * (WPAD * 2) + (k * 16 + acol) * 2);
            mma16816(acc[ot], af, bf[k]);
        }
    }
    __half* hrow = g_hbuf + (size_t)n * FEAT;
#pragma unroll
    for (int ot = 0; ot < 4; ot++) {
        int oa = ot * 16 + r, ob = oa + 8;
        float ba = sB2[oa], bb = sB2[ob];
        float f0 = fmaxf(acc[ot][0] + ba, 0.f), f1 = fmaxf(acc[ot][1] + ba, 0.f);
        float f2 = fmaxf(acc[ot][2] + bb, 0.f), f3 = fmaxf(acc[ot][3] + bb, 0.f);
        *(__half2*)(hrow + oa * 8 + 2 * q) = __floats2half2_rn(f0, f1);
        *(__half2*)(hrow + ob * 8 + 2 * q) = __floats2half2_rn(f2, f3);
        if (layer == 4) {
            atomicAdd(&sPool[oa * 8 + 2 * q],     f0);
            atomicAdd(&sPool[oa * 8 + 2 * q + 1], f1);
            atomicAdd(&sPool[ob * 8 + 2 * q],     f2);
            atomicAdd(&sPool[ob * 8 + 2 * q + 1], f3);
        }
        float sa = f0 + f1, qa = f0 * f0 + f1 * f1;
        float sb = f2 + f3, qb = f2 * f2 + f3 * f3;
        sa += __shfl_xor_sync(0xffffffffu, sa, 1); sa += __shfl_xor_sync(0xffffffffu, sa, 2);
        qa += __shfl_xor_sync(0xffffffffu, qa, 1); qa += __shfl_xor_sync(0xffffffffu, qa, 2);
        sb += __shfl_xor_sync(0xffffffffu, sb, 1); sb += __shfl_xor_sync(0xffffffffu, sb, 2);
        qb += __shfl_xor_sync(0xffffffffu, qb, 1); qb += __shfl_xor_sync(0xffffffffu, qb, 2);
        if (q == 0) {
            atomicAdd(&sStats[oa], sa);
            atomicAdd(&sStats[64 + oa], qa);
            atomicAdd(&sStats[ob], sb);
            atomicAdd(&sStats[64 + ob], qb);
        }
    }
    __syncthreads();
    if (t < 128) atomicAdd(&g_stats[layer * 128 + t], sStats[t]);
    if (layer == 4) atomicAdd(&g_pool[t], sPool[t]);
}

// ---------------- head ----------------
__global__ void k_final(const float* __restrict__ gamma, const float* __restrict__ beta,
                        const float* __restrict__ wout, const float* __restrict__ bout,
                        float* __restrict__ o) {
    __shared__ float sSc[64], sSh[64];
    int t = threadIdx.x;   // 64 threads
    {
        const float* st = g_stats + 4 * 128;
        float inv = 1.0f / 160000.0f;
        float mean = st[t] * inv;
        float var = st[64 + t] * inv - mean * mean;
        float sc = gamma[t] * rsqrtf(var + 1e-5f);
        sSc[t] = sc;
        sSh[t] = beta[t] - mean * sc;
    }
    __syncthreads();
    if (t < 8) {
        float acc = bout[0];
        for (int c = 0; c < 64; c++)
            acc += wout[c] * (sSc[c] * g_pool[c * 8 + t] * (1.0f / N_NODES) + sSh[c]);
        o[t] = 1.0f / (1.0f + expf(-acc));
    }
}

// ---------------- launch ----------------
extern "C" void kernel_launch(void* const* d_in, const int* in_sizes, int n_in,
                              void* d_out, int out_size) {
    const float* x     = (const float*)d_in[0];
    const void*  ei    = d_in[1];
    // d_in[2] = batch (unused, all zeros)
    const float* w10   = (const float*)d_in[3];
    const float* w1    = (const float*)d_in[4];
    const float* b1    = (const float*)d_in[5];
    const float* w2    = (const float*)d_in[6];
    const float* b2    = (const float*)d_in[7];
    const float* gamma = (const float*)d_in[8];
    const float* beta  = (const float*)d_in[9];
    const float* wout  = (const float*)d_in[10];
    const float* bout  = (const float*)d_in[11];
    float* out = (float*)d_out;

    k_init<<<(5 * 4096 + 255) / 256, 256>>>(ei, w1, w2);
    k_hist<<<(N_EDGES / 4 + 255) / 256, 256>>>(ei);
    k_scan<<<1, 1024>>>();
    k_fill<<<(N_EDGES / 2 + 255) / 256, 256>>>(ei);

    k_layer0<<<N_NODES / 8, 256>>>(x, w10, b1, b2);
    for (int i = 1; i <= 4; i++) {
        k_gather<<<N_NODES / 4, 256>>>(i, gamma + (i - 1) * 64, beta + (i - 1) * 64);
        k_mlp<<<N_NODES / 16, 512>>>(i, b1 + i * 64, b2 + i * 64);
    }
    k_final<<<1, 64>>>(gamma + 4 * 64, beta + 4 * 64, wout, bout, out);
}

// round 17
// speedup vs baseline: 1.0456x; 1.0456x over previous
#include <cuda_runtime.h>
#include <cuda_fp16.h>
#include <cstdint>

// GIN: 5 layers, N=20000 nodes, E=320000 edges, HIDDEN=64, M=8.
//  - CSR build per launch (vectorized histogram + shfl scan + fill).
//  - h/z fp16, L2-resident. k_gather: fp16 CSR gather + per-thread BN-affine
//    (no smem/barrier) -> z. k_layer0 + k_mlp: HMMA GEMMs, weight smem rows
//    padded to 144B (conflict-free ldmatrix), 8 nodes/block. Layer-4 epilogue
//    accumulates the mean-pool. k_final folds layer-4 BN into the head.

#define N_NODES 20000
#define N_EDGES 320000
#define HID 64
#define MDIM 8
#define FEAT (HID*MDIM)   // 512 elements per node
#define WPAD 72           // padded halves per weight row (144B, 9 uint4)

typedef unsigned long long ull;

// ---------------- device scratch ----------------
__device__ __half g_hbuf[N_NODES * FEAT];   // h fp16 (gather + pool source)
__device__ __half g_z16[N_NODES * FEAT];    // z fp16 scratch
__device__ int    g_rowptr[N_NODES + 1];
__device__ int    g_count[N_NODES];
__device__ int    g_fill[N_NODES];
__device__ int    g_srce[N_EDGES];
__device__ float  g_stats[5 * 128];         // per layer: sum[64], sumsq[64]
__device__ __half g_W1h[4 * 4096];          // W1 layers 1..4, [o][c] fp16
__device__ __half g_W2h[5 * 4096];          // W2 layers 0..4, [o][c] fp16
__device__ float  g_pool[FEAT];
__device__ int    g_is64;

// ---------------- helpers ----------------
__device__ __forceinline__ uint32_t smem_u32(const void* p) {
    return (uint32_t)__cvta_generic_to_shared(p);
}
__device__ __forceinline__ void ldmA(unsigned a[4], uint32_t addr) {
    asm volatile("ldmatrix.sync.aligned.m8n8.x4.shared.b16 {%0,%1,%2,%3}, [%4];"
        : "=r"(a[0]), "=r"(a[1]), "=r"(a[2]), "=r"(a[3]) : "r"(addr));
}
__device__ __forceinline__ void ldmBt(unsigned b[2], uint32_t addr) {
    asm volatile("ldmatrix.sync.aligned.m8n8.x2.trans.shared.b16 {%0,%1}, [%2];"
        : "=r"(b[0]), "=r"(b[1]) : "r"(addr));
}
__device__ __forceinline__ void mma16816(float d[4], const unsigned a[4], const unsigned b[2]) {
    asm volatile("mma.sync.aligned.m16n8k16.row.col.f32.f16.f16.f32 "
        "{%0,%1,%2,%3}, {%4,%5,%6,%7}, {%8,%9}, {%0,%1,%2,%3};"
        : "+f"(d[0]), "+f"(d[1]), "+f"(d[2]), "+f"(d[3])
        : "r"(a[0]), "r"(a[1]), "r"(a[2]), "r"(a[3]), "r"(b[0]), "r"(b[1]));
}

// ---------------- setup: init + dtype detect + weight fp16 prep ----------------
__global__ void k_init(const void* ei, const float* __restrict__ w1,
                       const float* __restrict__ w2) {
    __shared__ int s_ok;
    if (threadIdx.x == 0) s_ok = 1;
    __syncthreads();
    int i = blockIdx.x * blockDim.x + threadIdx.x;
    if (i < N_NODES) { g_count[i] = 0; g_fill[i] = 0; }
    if (i < 5 * 128) g_stats[i] = 0.f;
    if (i < FEAT)    g_pool[i] = 0.f;
    if (i < 4 * 4096) g_W1h[i] = __float2half(w1[i]);
    if (i < 5 * 4096) g_W2h[i] = __float2half(w2[i]);
    if (blockIdx.x == 0 && threadIdx.x < 64) {
        if (((const ull*)ei)[threadIdx.x] >= (ull)N_NODES) atomicExch(&s_ok, 0);
    }
    __syncthreads();
    if (blockIdx.x == 0 && threadIdx.x == 0) g_is64 = s_ok;
}

// histogram: 4 edges per thread, vectorized loads
__global__ void k_hist(const void* ei) {
    int i = blockIdx.x * blockDim.x + threadIdx.x;
    if (i * 4 >= N_EDGES) return;
    int d0, d1, d2, d3;
    if (g_is64) {
        const longlong2* pd = (const longlong2*)((const long long*)ei + N_EDGES);
        longlong2 a = pd[i * 2], b = pd[i * 2 + 1];
        d0 = (int)a.x; d1 = (int)a.y; d2 = (int)b.x; d3 = (int)b.y;
    } else {
        int4 a = ((const int4*)((const int*)ei + N_EDGES))[i];
        d0 = a.x; d1 = a.y; d2 = a.z; d3 = a.w;
    }
    atomicAdd(&g_count[d0], 1);
    atomicAdd(&g_count[d1], 1);
    atomicAdd(&g_count[d2], 1);
    atomicAdd(&g_count[d3], 1);
}

// shfl scan; int4 loads AND int4 stores
__global__ void k_scan() {   // 1024 threads
    __shared__ int warpsum[32];
    const int CH = 20;
    int t = threadIdx.x;
    int lane = t & 31, wid = t >> 5;
    int base = t * CH;
    int raw[CH];
    bool full = (base + CH <= N_NODES);
    if (full) {
#pragma unroll
        for (int v4 = 0; v4 < 5; v4++) {
            int4 v = *(const int4*)(g_count + base + v4 * 4);
            raw[v4 * 4 + 0] = v.x; raw[v4 * 4 + 1] = v.y;
            raw[v4 * 4 + 2] = v.z; raw[v4 * 4 + 3] = v.w;
        }
    } else {
#pragma unroll
        for (int j = 0; j < CH; j++)
            raw[j] = (base + j < N_NODES) ? g_count[base + j] : 0;
    }
    int vals[CH];
    int local = 0;
#pragma unroll
    for (int j = 0; j < CH; j++) { vals[j] = local; local += raw[j]; }
    int inc = local;
#pragma unroll
    for (int off = 1; off < 32; off <<= 1) {
        int v = __shfl_up_sync(0xffffffffu, inc, off);
        if (lane >= off) inc += v;
    }
    if (lane == 31) warpsum[wid] = inc;
    __syncthreads();
    if (wid == 0) {
        int v = warpsum[lane];
        int inc2 = v;
#pragma unroll
        for (int off = 1; off < 32; off <<= 1) {
            int u = __shfl_up_sync(0xffffffffu, inc2, off);
            if (lane >= off) inc2 += u;
        }
        warpsum[lane] = inc2 - v;
    }
    __syncthreads();
    int toff = warpsum[wid] + inc - local;
    if (full) {
#pragma unroll
        for (int v4 = 0; v4 < 5; v4++) {
            int4 st;
            st.x = toff + vals[v4 * 4 + 0];
            st.y = toff + vals[v4 * 4 + 1];
            st.z = toff + vals[v4 * 4 + 2];
            st.w = toff + vals[v4 * 4 + 3];
            *(int4*)(g_rowptr + base + v4 * 4) = st;
        }
    } else {
#pragma unroll
        for (int j = 0; j < CH; j++)
            if (base + j < N_NODES) g_rowptr[base + j] = toff + vals[j];
    }
    if (t == 1023) g_rowptr[N_NODES] = toff + local;
}

// fill: 4 edges per thread, vectorized loads
__global__ void k_fill(const void* ei) {
    int i = blockIdx.x * blockDim.x + threadIdx.x;
    if (i * 4 >= N_EDGES) return;
    int s0, s1, s2, s3, d0, d1, d2, d3;
    if (g_is64) {
        const longlong2* ps = (const longlong2*)ei;
        const longlong2* pd = (const longlong2*)((const long long*)ei + N_EDGES);
        longlong2 a = ps[i * 2], b = ps[i * 2 + 1];
        longlong2 c = pd[i * 2], d = pd[i * 2 + 1];
        s0 = (int)a.x; s1 = (int)a.y; s2 = (int)b.x; s3 = (int)b.y;
        d0 = (int)c.x; d1 = (int)c.y; d2 = (int)d.x; d3 = (int)d.y;
    } else {
        int4 a = ((const int4*)ei)[i];
        int4 c = ((const int4*)((const int*)ei + N_EDGES))[i];
        s0 = a.x; s1 = a.y; s2 = a.z; s3 = a.w;
        d0 = c.x; d1 = c.y; d2 = c.z; d3 = c.w;
    }
    g_srce[g_rowptr[d0] + atomicAdd(&g_fill[d0], 1)] = s0;
    g_srce[g_rowptr[d1] + atomicAdd(&g_fill[d1], 1)] = s1;
    g_srce[g_rowptr[d2] + atomicAdd(&g_fill[d2], 1)] = s2;
    g_srce[g_rowptr[d3] + atomicAdd(&g_fill[d3], 1)] = s3;
}

// ---------------- layer 0: x-gather + outer-product GEMM1 + HMMA GEMM2 ----------
__global__ void __launch_bounds__(256) k_layer0(
    const float* __restrict__ x, const float* __restrict__ w10,
    const float* __restrict__ b1, const float* __restrict__ b2) {
    __shared__ __half sW2[64 * WPAD];
    __shared__ __half sZ[8 * FEAT];
    __shared__ float sStats[128];
    __shared__ float sW10[64], sB1[64], sB2[64];
    __shared__ float sZ0[64];
    int t = threadIdx.x;
    int w = t >> 5, lane = t & 31;
    if (t < 128) sStats[t] = 0.f;
    if (t < 64) { sW10[t] = w10[t]; sB1[t] = b1[t]; sB2[t] = b2[t]; }
    const uint4* w2src = (const uint4*)g_W2h;
#pragma unroll
    for (int rep = 0; rep < 2; rep++) {
        int j = t + rep * 256;
        int o = j >> 3, c8 = j & 7;
        ((uint4*)sW2)[o * 9 + c8] = w2src[j];
    }
    __syncthreads();

    int n = (blockIdx.x << 3) + w;
    int m = lane & 7, g = lane >> 3;
    int rs = g_rowptr[n], re = g_rowptr[n + 1];
    float z = (g == 0) ? x[n * 8 + m] : 0.f;
    for (int e = rs + g; e < re; e += 4)
        z += x[g_srce[e] * 8 + m];
    z += __shfl_xor_sync(0xffffffffu, z, 8);
    z += __shfl_xor_sync(0xffffffffu, z, 16);
    if (lane < 8) sZ0[w * 8 + m] = z;
    __syncwarp();
    float zf[8];
#pragma unroll
    for (int j = 0; j < 8; j++) zf[j] = sZ0[w * 8 + j];
    int orow0 = lane * 2;
#pragma unroll
    for (int r2 = 0; r2 < 2; r2++) {
        int o = orow0 + r2;
        float wv = sW10[o], b = sB1[o];
        __half2 p0 = __floats2half2_rn(fmaxf(wv * zf[0] + b, 0.f), fmaxf(wv * zf[1] + b, 0.f));
        __half2 p1 = __floats2half2_rn(fmaxf(wv * zf[2] + b, 0.f), fmaxf(wv * zf[3] + b, 0.f));
        __half2 p2 = __floats2half2_rn(fmaxf(wv * zf[4] + b, 0.f), fmaxf(wv * zf[5] + b, 0.f));
        __half2 p3 = __floats2half2_rn(fmaxf(wv * zf[6] + b, 0.f), fmaxf(wv * zf[7] + b, 0.f));
        uint4 hv;
        hv.x = *(unsigned*)&p0; hv.y = *(unsigned*)&p1;
        hv.z = *(unsigned*)&p2; hv.w = *(unsigned*)&p3;
        *(uint4*)(sZ + (w << 9) + o * 8) = hv;
    }
    __syncwarp();

    uint32_t zbase = smem_u32(sZ + w * FEAT);
    int r = lane >> 2, q = lane & 3;
    int arow = lane & 15, acol = (lane >> 4) << 3;
    unsigned bf[4][2];
#pragma unroll
    for (int k = 0; k < 4; k++)
        ldmBt(bf[k], zbase + ((k * 16 + (lane & 15)) * 8) * 2);
    uint32_t w2base = smem_u32(sW2);
    float acc[4][4];
#pragma unroll
    for (int ot = 0; ot < 4; ot++) {
#pragma unroll
        for (int i = 0; i < 4; i++) acc[ot][i] = 0.f;
#pragma unroll
        for (int k = 0; k < 4; k++) {
            unsigned af[4];
            ldmA(af, w2base + (ot * 16 + arow) * (WPAD * 2) + (k * 16 + acol) * 2);
            mma16816(acc[ot], af, bf[k]);
        }
    }
    __half* hrow = g_hbuf + (size_t)n * FEAT;
#pragma unroll
    for (int ot = 0; ot < 4; ot++) {
        int oa = ot * 16 + r, ob = oa + 8;
        float ba = sB2[oa], bb = sB2[ob];
        float f0 = fmaxf(acc[ot][0] + ba, 0.f), f1 = fmaxf(acc[ot][1] + ba, 0.f);
        float f2 = fmaxf(acc[ot][2] + bb, 0.f), f3 = fmaxf(acc[ot][3] + bb, 0.f);
        *(__half2*)(hrow + oa * 8 + 2 * q) = __floats2half2_rn(f0, f1);
        *(__half2*)(hrow + ob * 8 + 2 * q) = __floats2half2_rn(f2, f3);
        float sa = f0 + f1, qa = f0 * f0 + f1 * f1;
        float sb = f2 + f3, qb = f2 * f2 + f3 * f3;
        sa += __shfl_xor_sync(0xffffffffu, sa, 1); sa += __shfl_xor_sync(0xffffffffu, sa, 2);
        qa += __shfl_xor_sync(0xffffffffu, qa, 1); qa += __shfl_xor_sync(0xffffffffu, qa, 2);
        sb += __shfl_xor_sync(0xffffffffu, sb, 1); sb += __shfl_xor_sync(0xffffffffu, sb, 2);
        qb += __shfl_xor_sync(0xffffffffu, qb, 1); qb += __shfl_xor_sync(0xffffffffu, qb, 2);
        if (q == 0) {
            atomicAdd(&sStats[oa], sa);
            atomicAdd(&sStats[64 + oa], qa);
            atomicAdd(&sStats[ob], sb);
            atomicAdd(&sStats[64 + ob], qb);
        }
    }
    __syncthreads();
    if (t < 128) atomicAdd(&g_stats[t], sStats[t]);
}

// ---------------- gather (layers 1..4): fp16 CSR gather, per-thread affine ----
// 64 threads per node; no smem, no block barrier — warps fully independent.
__device__ __forceinline__ void acc8(float a[8], uint4 v) {
    float2 p;
    p = __half22float2(*(const __half2*)&v.x); a[0] += p.x; a[1] += p.y;
    p = __half22float2(*(const __half2*)&v.y); a[2] += p.x; a[3] += p.y;
    p = __half22float2(*(const __half2*)&v.z); a[4] += p.x; a[5] += p.y;
    p = __half22float2(*(const __half2*)&v.w); a[6] += p.x; a[7] += p.y;
}

__global__ void __launch_bounds__(256) k_gather(
    int layer, const float* __restrict__ gamma, const float* __restrict__ beta) {
    const uint4* __restrict__ in = (const uint4*)g_hbuf;
    int t = threadIdx.x;
    int grp = t >> 6;
    int l = t & 63;
    int n = (blockIdx.x << 2) + grp;
    // per-thread BN affine of previous layer (only own channel needed)
    const float* st = g_stats + (layer - 1) * 128;
    float inv = 1.0f / 160000.0f;
    float mean = st[l] * inv;
    float var = st[64 + l] * inv - mean * mean;
    float sc = gamma[l] * rsqrtf(var + 1e-5f);
    float sh = beta[l] - mean * sc;
    int rs = g_rowptr[n], re = g_rowptr[n + 1];
    float a[8] = {0,0,0,0,0,0,0,0}, b[8] = {0,0,0,0,0,0,0,0};
    acc8(a, in[(size_t)n * 64 + l]);   // self
    int e = rs;
    for (; e + 4 <= re; e += 4) {
        uint4 v0 = in[(size_t)g_srce[e]     * 64 + l];
        uint4 v1 = in[(size_t)g_srce[e + 1] * 64 + l];
        uint4 v2 = in[(size_t)g_srce[e + 2] * 64 + l];
        uint4 v3 = in[(size_t)g_srce[e + 3] * 64 + l];
        acc8(a, v0); acc8(b, v1); acc8(a, v2); acc8(b, v3);
    }
    for (; e < re; e++) acc8(a, in[(size_t)g_srce[e] * 64 + l]);
    float shd = sh * (float)(re - rs + 1);
    float f0 = sc * (a[0] + b[0]) + shd, f1 = sc * (a[1] + b[1]) + shd;
    float f2 = sc * (a[2] + b[2]) + shd, f3 = sc * (a[3] + b[3]) + shd;
    float f4 = sc * (a[4] + b[4]) + shd, f5 = sc * (a[5] + b[5]) + shd;
    float f6 = sc * (a[6] + b[6]) + shd, f7 = sc * (a[7] + b[7]) + shd;
    __half2 h0 = __floats2half2_rn(f0, f1);
    __half2 h1 = __floats2half2_rn(f2, f3);
    __half2 h2 = __floats2half2_rn(f4, f5);
    __half2 h3 = __floats2half2_rn(f6, f7);
    uint4 hv;
    hv.x = *(unsigned*)&h0; hv.y = *(unsigned*)&h1;
    hv.z = *(unsigned*)&h2; hv.w = *(unsigned*)&h3;
    *(uint4*)(g_z16 + (size_t)n * FEAT + (l << 3)) = hv;
}

// ---------------- MLP (layers 1..4): HMMA GEMM pair, 8 nodes/block ----------
__global__ void __launch_bounds__(256) k_mlp(
    int layer, const float* __restrict__ b1, const float* __restrict__ b2) {
    __shared__ __half sW1[64 * WPAD];
    __shared__ __half sW2[64 * WPAD];
    __shared__ __half sZ[8 * FEAT];
    __shared__ float sStats[128];
    __shared__ float sPool[FEAT];
    __shared__ float sB1[64], sB2[64];
    int t = threadIdx.x;
    int w = t >> 5, lane = t & 31;
    if (t < 128) sStats[t] = 0.f;
    if (t < 64) { sB1[t] = b1[t]; sB2[t] = b2[t]; }
    if (layer == 4) { sPool[t] = 0.f; sPool[t + 256] = 0.f; }
    const uint4* w1src = (const uint4*)(g_W1h + (size_t)(layer - 1) * 4096);
    const uint4* w2src = (const uint4*)(g_W2h + (size_t)layer * 4096);
    const uint4* zsrc  = (const uint4*)(g_z16 + (size_t)(blockIdx.x << 3) * FEAT);
#pragma unroll
    for (int rep = 0; rep < 2; rep++) {
        int j = t + rep * 256;
        int o = j >> 3, c8 = j & 7;
        ((uint4*)sW1)[o * 9 + c8] = w1src[j];
        ((uint4*)sW2)[o * 9 + c8] = w2src[j];
    }
    ((uint4*)sZ)[t]       = zsrc[t];
    ((uint4*)sZ)[t + 256] = zsrc[t + 256];
    __syncthreads();

    int n = (blockIdx.x << 3) + w;
    uint32_t zbase = smem_u32(sZ + w * FEAT);
    int r = lane >> 2, q = lane & 3;
    int arow = lane & 15, acol = (lane >> 4) << 3;

    // ---- GEMM1 ----
    unsigned bf[4][2];
#pragma unroll
    for (int k = 0; k < 4; k++)
        ldmBt(bf[k], zbase + ((k * 16 + (lane & 15)) * 8) * 2);
    uint32_t w1base = smem_u32(sW1);
    float acc[4][4];
#pragma unroll
    for (int ot = 0; ot < 4; ot++) {
#pragma unroll
        for (int i = 0; i < 4; i++) acc[ot][i] = 0.f;
#pragma unroll
        for (int k = 0; k < 4; k++) {
            unsigned af[4];
            ldmA(af, w1base + (ot * 16 + arow) * (WPAD * 2) + (k * 16 + acol) * 2);
            mma16816(acc[ot], af, bf[k]);
        }
    }
#pragma unroll
    for (int ot = 0; ot < 4; ot++) {
        int oa = ot * 16 + r, ob = oa + 8;
        float ba = sB1[oa], bb = sB1[ob];
        __half2 ya = __floats2half2_rn(fmaxf(acc[ot][0] + ba, 0.f), fmaxf(acc[ot][1] + ba, 0.f));
        __half2 yb = __floats2half2_rn(fmaxf(acc[ot][2] + bb, 0.f), fmaxf(acc[ot][3] + bb, 0.f));
        *(__half2*)(sZ + w * FEAT + oa * 8 + 2 * q) = ya;
        *(__half2*)(sZ + w * FEAT + ob * 8 + 2 * q) = yb;
    }
    __syncwarp();

    // ---- GEMM2 ----
#pragma unroll
    for (int k = 0; k < 4; k++)
        ldmBt(bf[k], zbase + ((k * 16 + (lane & 15)) * 8) * 2);
    uint32_t w2base = smem_u32(sW2);
#pragma unroll
    for (int ot = 0; ot < 4; ot++) {
#pragma unroll
        for (int i = 0; i < 4; i++) acc[ot][i] = 0.f;
#pragma unroll
        for (int k = 0; k < 4; k++) {
            unsigned af[4];
            ldmA(af, w2base + (ot * 16 + arow) * (WPAD * 2) + (k * 16 + acol) * 2);
            mma16816(acc[ot], af, bf[k]);
        }
    }
    __half* hrow = g_hbuf + (size_t)n * FEAT;
#pragma unroll
    for (int ot = 0; ot < 4; ot++) {
        int oa = ot * 16 + r, ob = oa + 8;
        float ba = sB2[oa], bb = sB2[ob];
        float f0 = fmaxf(acc[ot][0] + ba, 0.f), f1 = fmaxf(acc[ot][1] + ba, 0.f);
        float f2 = fmaxf(acc[ot][2] + bb, 0.f), f3 = fmaxf(acc[ot][3] + bb, 0.f);
        *(__half2*)(hrow + oa * 8 + 2 * q) = __floats2half2_rn(f0, f1);
        *(__half2*)(hrow + ob * 8 + 2 * q) = __floats2half2_rn(f2, f3);
        if (layer == 4) {
            atomicAdd(&sPool[oa * 8 + 2 * q],     f0);
            atomicAdd(&sPool[oa * 8 + 2 * q + 1], f1);
            atomicAdd(&sPool[ob * 8 + 2 * q],     f2);
            atomicAdd(&sPool[ob * 8 + 2 * q + 1], f3);
        }
        float sa = f0 + f1, qa = f0 * f0 + f1 * f1;
        float sb = f2 + f3, qb = f2 * f2 + f3 * f3;
        sa += __shfl_xor_sync(0xffffffffu, sa, 1); sa += __shfl_xor_sync(0xffffffffu, sa, 2);
        qa += __shfl_xor_sync(0xffffffffu, qa, 1); qa += __shfl_xor_sync(0xffffffffu, qa, 2);
        sb += __shfl_xor_sync(0xffffffffu, sb, 1); sb += __shfl_xor_sync(0xffffffffu, sb, 2);
        qb += __shfl_xor_sync(0xffffffffu, qb, 1); qb += __shfl_xor_sync(0xffffffffu, qb, 2);
        if (q == 0) {
            atomicAdd(&sStats[oa], sa);
            atomicAdd(&sStats[64 + oa], qa);
            atomicAdd(&sStats[ob], sb);
            atomicAdd(&sStats[64 + ob], qb);
        }
    }
    __syncthreads();
    if (t < 128) atomicAdd(&g_stats[layer * 128 + t], sStats[t]);
    if (layer == 4) {
        atomicAdd(&g_pool[t], sPool[t]);
        atomicAdd(&g_pool[t + 256], sPool[t + 256]);
    }
}

// ---------------- head ----------------
__global__ void k_final(const float* __restrict__ gamma, const float* __restrict__ beta,
                        const float* __restrict__ wout, const float* __restrict__ bout,
                        float* __restrict__ o) {
    __shared__ float sSc[64], sSh[64];
    int t = threadIdx.x;   // 64 threads
    {
        const float* st = g_stats + 4 * 128;
        float inv = 1.0f / 160000.0f;
        float mean = st[t] * inv;
        float var = st[64 + t] * inv - mean * mean;
        float sc = gamma[t] * rsqrtf(var + 1e-5f);
        sSc[t] = sc;
        sSh[t] = beta[t] - mean * sc;
    }
    __syncthreads();
    if (t < 8) {
        float acc = bout[0];
        for (int c = 0; c < 64; c++)
            acc += wout[c] * (sSc[c] * g_pool[c * 8 + t] * (1.0f / N_NODES) + sSh[c]);
        o[t] = 1.0f / (1.0f + expf(-acc));
    }
}

// ---------------- launch ----------------
extern "C" void kernel_launch(void* const* d_in, const int* in_sizes, int n_in,
                              void* d_out, int out_size) {
    const float* x     = (const float*)d_in[0];
    const void*  ei    = d_in[1];
    // d_in[2] = batch (unused, all zeros)
    const float* w10   = (const float*)d_in[3];
    const float* w1    = (const float*)d_in[4];
    const float* b1    = (const float*)d_in[5];
    const float* w2    = (const float*)d_in[6];
    const float* b2    = (const float*)d_in[7];
    const float* gamma = (const float*)d_in[8];
    const float* beta  = (const float*)d_in[9];
    const float* wout  = (const float*)d_in[10];
    const float* bout  = (const float*)d_in[11];
    float* out = (float*)d_out;

    k_init<<<(5 * 4096 + 255) / 256, 256>>>(ei, w1, w2);
    k_hist<<<(N_EDGES / 4 + 255) / 256, 256>>>(ei);
    k_scan<<<1, 1024>>>();
    k_fill<<<(N_EDGES / 4 + 255) / 256, 256>>>(ei);

    k_layer0<<<N_NODES / 8, 256>>>(x, w10, b1, b2);
    for (int i = 1; i <= 4; i++) {
        k_gather<<<N_NODES / 4, 256>>>(i, gamma + (i - 1) * 64, beta + (i - 1) * 64);
        k_mlp<<<N_NODES / 8, 256>>>(i, b1 + i * 64, b2 + i * 64);
    }
    k_final<<<1, 64>>>(gamma + 4 * 64, beta + 4 * 64, wout, bout, out);
}